// round 5
// baseline (speedup 1.0000x reference)
#include <cuda_runtime.h>
#include <math_constants.h>
#include <cstdint>

// FLoss: weighted BCE, weights = W / (dist_to_argmax_centroid + 1)
// input  d_in[0]: [B,1,T,W,W] f32  (same linear layout as [B,T,W,W])
// target d_in[1]: [B,T,W,W]   f32
// out: scalar f32 = -mean(w * (t*clip(log p,-100) + (1-t)*clip(log1p(-p),-100)))
//
// Fully fused: one CTA per 256x256 frame, 3 passes over the frame with the
// target kept L1-resident (228KB L1 vs 256KB frame; alternating scan
// direction defeats LRU sequential-sweep thrashing).

#define FRAME_ELEMS4 16384                 // 65536 elems / 4
#define MAX_FRAMES 4096

__device__ double   g_acc;                 // starts 0; last block resets to 0
__device__ unsigned g_done;                // starts 0; last block resets to 0

#define LOG2_CLAMP (-144.26950408889634f)  // -100 / ln(2)
#define LN2F        (0.6931471805599453f)

__global__ __launch_bounds__(1024, 1) void floss_fused_kernel(const float* __restrict__ inp,
                                                              const float* __restrict__ tgt,
                                                              float* __restrict__ out,
                                                              double inv_n)
{
    const int f   = blockIdx.x;
    const int tid = threadIdx.x;
    const float4* T = reinterpret_cast<const float4*>(tgt) + (size_t)f * FRAME_ELEMS4;
    const float4* P = reinterpret_cast<const float4*>(inp) + (size_t)f * FRAME_ELEMS4;

    __shared__ float s_wmax[32];
    __shared__ float s_gmax, s_sx, s_sy, s_cnt, s_cx, s_cy;

    // ---------------- pass 1: frame max (forward scan, fills L1) -----------
    float m0 = -CUDART_INF_F, m1 = -CUDART_INF_F, m2 = -CUDART_INF_F, m3 = -CUDART_INF_F;
    #pragma unroll
    for (int k = 0; k < 16; k++) {
        const float4 v = __ldg(T + tid + k * 1024);
        m0 = fmaxf(m0, v.x); m1 = fmaxf(m1, v.y);
        m2 = fmaxf(m2, v.z); m3 = fmaxf(m3, v.w);
    }
    float lmax = fmaxf(fmaxf(m0, m1), fmaxf(m2, m3));

    #pragma unroll
    for (int o = 16; o; o >>= 1) lmax = fmaxf(lmax, __shfl_xor_sync(0xffffffffu, lmax, o));
    if ((tid & 31) == 0) s_wmax[tid >> 5] = lmax;
    if (tid == 0) { s_sx = 0.f; s_sy = 0.f; s_cnt = 0.f; }
    __syncthreads();
    if (tid < 32) {
        float m = s_wmax[tid];
        #pragma unroll
        for (int o = 16; o; o >>= 1) m = fmaxf(m, __shfl_xor_sync(0xffffffffu, m, o));
        if (tid == 0) s_gmax = m;
    }
    __syncthreads();

    // ---------------- pass 2: centroid of argmax pixels (reverse scan) -----
    // Exact float-equality mask, identical to reference (target == max).
    const float gmax = s_gmax;
    #pragma unroll
    for (int k = 15; k >= 0; k--) {
        const int e4 = tid + k * 1024;
        const float4 v = __ldg(T + e4);
        const int e = e4 * 4;
        if (v.x == gmax || v.y == gmax || v.z == gmax || v.w == gmax) {   // rare
            const float row  = (float)(e >> 8);
            const float col0 = (float)(e & 255);
            if (v.x == gmax) { atomicAdd(&s_cnt, 1.f); atomicAdd(&s_sx, row); atomicAdd(&s_sy, col0 + 0.f); }
            if (v.y == gmax) { atomicAdd(&s_cnt, 1.f); atomicAdd(&s_sx, row); atomicAdd(&s_sy, col0 + 1.f); }
            if (v.z == gmax) { atomicAdd(&s_cnt, 1.f); atomicAdd(&s_sx, row); atomicAdd(&s_sy, col0 + 2.f); }
            if (v.w == gmax) { atomicAdd(&s_cnt, 1.f); atomicAdd(&s_sx, row); atomicAdd(&s_sy, col0 + 3.f); }
        }
    }
    __syncthreads();
    if (tid == 0) { s_cx = s_sx / s_cnt; s_cy = s_sy / s_cnt; }
    __syncthreads();
    const float cx = s_cx;
    const float cy = s_cy;

    // ---------------- pass 3: weighted BCE (forward scan) ------------------
    // target: mostly L1 hits; input: streaming, evict-first (.cs) so it does
    // not displace the L1-resident target.
    float lsum = 0.f;
    #pragma unroll
    for (int k = 0; k < 16; k++) {
        const int e4 = tid + k * 1024;
        const float4 t4 = __ldg (T + e4);
        const float4 p4 = __ldcs(P + e4);

        const int e = e4 * 4;
        const float row  = (float)(e >> 8);
        const float col0 = (float)(e & 255);
        const float di   = row - cx;
        const float di2  = di * di;

        const float pv[4] = {p4.x, p4.y, p4.z, p4.w};
        const float tv[4] = {t4.x, t4.y, t4.z, t4.w};

        #pragma unroll
        for (int c = 0; c < 4; c++) {
            const float dj = (col0 + (float)c) - cy;
            const float s  = fmaf(dj, dj, di2);
            float dist;
            asm("sqrt.approx.f32 %0, %1;" : "=f"(dist) : "f"(s));   // sqrt.approx(0)=0
            const float wgt = __fdividef(256.0f, dist + 1.0f);

            const float p = pv[c];
            const float t = tv[c];
            float lp2, lq2;
            asm("lg2.approx.f32 %0, %1;" : "=f"(lp2) : "f"(p));
            asm("lg2.approx.f32 %0, %1;" : "=f"(lq2) : "f"(1.0f - p));
            lp2 = fmaxf(lp2, LOG2_CLAMP);
            lq2 = fmaxf(lq2, LOG2_CLAMP);
            const float term = fmaf(t, lp2 - lq2, lq2);   // log2 domain
            lsum = fmaf(wgt, term, lsum);
        }
    }
    lsum *= LN2F;

    // ---------------- reduce + last-block finalize --------------------------
    __shared__ double s_acc;
    if (tid == 0) s_acc = 0.0;
    __syncthreads();

    #pragma unroll
    for (int o = 16; o; o >>= 1) lsum += __shfl_xor_sync(0xffffffffu, lsum, o);
    if ((tid & 31) == 0) atomicAdd(&s_acc, (double)lsum);
    __syncthreads();

    if (tid == 0) {
        atomicAdd(&g_acc, s_acc);
        __threadfence();
        const unsigned tk = atomicAdd(&g_done, 1u);
        if (tk == gridDim.x - 1) {                 // last CTA to finish
            const double total = atomicAdd(&g_acc, 0.0);
            out[0] = (float)(-total * inv_n);
            // reset for the next graph replay (deterministic: runs after all
            // CTAs of this replay have accumulated)
            g_acc  = 0.0;
            __threadfence();
            atomicExch(&g_done, 0u);
        }
    }
}

extern "C" void kernel_launch(void* const* d_in, const int* in_sizes, int n_in,
                              void* d_out, int out_size)
{
    const float* inp = (const float*)d_in[0];
    const float* tgt = (const float*)d_in[1];
    float* out = (float*)d_out;

    const int n       = in_sizes[1];       // B*T*W*W
    const int nframes = n >> 16;           // 65536 elems per frame

    floss_fused_kernel<<<nframes, 1024>>>(inp, tgt, out, 1.0 / (double)n);
}

// round 6
// speedup vs baseline: 1.1210x; 1.1210x over previous
#include <cuda_runtime.h>
#include <math_constants.h>
#include <cstdint>

// FLoss: weighted BCE, weights = W / (dist_to_argmax_centroid + 1)
// input  d_in[0]: [B,1,T,W,W] f32  (same linear layout as [B,T,W,W])
// target d_in[1]: [B,T,W,W]   f32
// out: scalar f32 = -mean(w * (t*clip(log p,-100) + (1-t)*clip(log1p(-p),-100)))

#define FRAME_ELEMS4 16384                 // 65536 elems / 4
#define TILES_PER_FRAME 8
#define TILE_F4 (FRAME_ELEMS4 / TILES_PER_FRAME)   // 2048 float4
#define MAX_FRAMES 4096

__device__ float    g_cx[MAX_FRAMES];
__device__ float    g_cy[MAX_FRAMES];
__device__ double   g_acc;
__device__ unsigned g_done;

#define LOG2_CLAMP (-144.26950408889634f)  // -100 / ln(2)
#define LN2F        (0.6931471805599453f)

// ---------------------------------------------------------------------------
// Kernel 1: per-frame max + centroid, single pass, branchless 4-chain.
// One CTA (1024 threads) per frame. Measured ~7.6 TB/s — at roofline.
// ---------------------------------------------------------------------------
__global__ __launch_bounds__(1024) void frame_stats_kernel(const float* __restrict__ tgt)
{
    const int f   = blockIdx.x;
    const int tid = threadIdx.x;
    const float4* base = reinterpret_cast<const float4*>(tgt) + (size_t)f * FRAME_ELEMS4;

    float lm[4], cn[4], sx[4], sy[4];
    #pragma unroll
    for (int c = 0; c < 4; c++) { lm[c] = -CUDART_INF_F; cn[c] = 0.f; sx[c] = 0.f; sy[c] = 0.f; }

    #pragma unroll
    for (int k = 0; k < 16; k++) {
        const int e4 = tid + k * 1024;
        const float4 v = __ldg(base + e4);
        const int e = e4 * 4;
        const float row  = (float)(e >> 8);
        const float col0 = (float)(e & 255);
        const float vals[4] = {v.x, v.y, v.z, v.w};
        #pragma unroll
        for (int c = 0; c < 4; c++) {
            const float val = vals[c];
            const float col = col0 + (float)c;
            const bool gt = (val >  lm[c]);
            const bool eq = (val == lm[c]);
            cn[c] = gt ? 1.f : (cn[c] + (eq ? 1.f : 0.f));
            sx[c] = gt ? row : (sx[c] + (eq ? row : 0.f));
            sy[c] = gt ? col : (sy[c] + (eq ? col : 0.f));
            lm[c] = fmaxf(lm[c], val);
        }
    }

    float lmax = lm[0], cnt = cn[0], tsx = sx[0], tsy = sy[0];
    #pragma unroll
    for (int c = 1; c < 4; c++) {
        if (lm[c] > lmax)       { lmax = lm[c]; cnt = cn[c]; tsx = sx[c]; tsy = sy[c]; }
        else if (lm[c] == lmax) { cnt += cn[c]; tsx += sx[c]; tsy += sy[c]; }
    }

    __shared__ float s_wmax[32];
    __shared__ float s_gmax, s_sx, s_sy, s_cnt;

    float wm = lmax;
    #pragma unroll
    for (int o = 16; o; o >>= 1) wm = fmaxf(wm, __shfl_xor_sync(0xffffffffu, wm, o));
    if ((tid & 31) == 0) s_wmax[tid >> 5] = wm;
    if (tid == 0) { s_sx = 0.f; s_sy = 0.f; s_cnt = 0.f; }
    __syncthreads();
    if (tid < 32) {
        float m = s_wmax[tid];
        #pragma unroll
        for (int o = 16; o; o >>= 1) m = fmaxf(m, __shfl_xor_sync(0xffffffffu, m, o));
        if (tid == 0) s_gmax = m;
    }
    __syncthreads();

    if (lmax == s_gmax) {
        atomicAdd(&s_cnt, cnt);
        atomicAdd(&s_sx,  tsx);
        atomicAdd(&s_sy,  tsy);
    }
    __syncthreads();

    if (tid == 0) {
        g_cx[f] = s_sx / s_cnt;
        g_cy[f] = s_sy / s_cnt;
        if (f == 0) { g_acc = 0.0; g_done = 0u; }   // per-replay reset (before loss)
    }
}

// ---------------------------------------------------------------------------
// Kernel 2: weighted BCE. 8 CTAs/frame, 8 iters/thread, unroll 2 (MLP=4,
// low register pressure), occupancy-capped regs via launch_bounds(256, 6).
// ---------------------------------------------------------------------------
__global__ __launch_bounds__(256, 6) void loss_kernel(const float* __restrict__ inp,
                                                      const float* __restrict__ tgt,
                                                      float* __restrict__ out,
                                                      double inv_n)
{
    const int tile = blockIdx.x;
    const int f    = tile >> 3;
    const int tbase = (tile & 7) * TILE_F4;          // float4 offset within frame
    const float cx = g_cx[f];
    const float cy = g_cy[f];

    const float4* P = reinterpret_cast<const float4*>(inp) + (size_t)f * FRAME_ELEMS4 + tbase;
    const float4* T = reinterpret_cast<const float4*>(tgt) + (size_t)f * FRAME_ELEMS4 + tbase;

    float lsum = 0.f;

    #pragma unroll 2
    for (int k = 0; k < 8; k++) {
        const int idx4 = k * 256 + threadIdx.x;
        const float4 p4 = __ldcs(P + idx4);
        const float4 t4 = __ldg (T + idx4);

        const int e4g = tbase + idx4;                // global float4 idx in frame
        const float row  = (float)(e4g >> 6);        // (e4*4) >> 8
        const float col0 = (float)((e4g & 63) * 4);
        const float di   = row - cx;
        const float di2  = di * di;

        const float pv[4] = {p4.x, p4.y, p4.z, p4.w};
        const float tv[4] = {t4.x, t4.y, t4.z, t4.w};

        #pragma unroll
        for (int c = 0; c < 4; c++) {
            const float dj = (col0 + (float)c) - cy;
            const float s  = fmaf(dj, dj, di2);
            float dist, wrcp;
            asm("sqrt.approx.f32 %0, %1;" : "=f"(dist) : "f"(s));     // sqrt.approx(0)=0
            asm("rcp.approx.f32 %0, %1;"  : "=f"(wrcp) : "f"(dist + 1.0f));
            const float wgt = 256.0f * wrcp;

            const float p = pv[c];
            const float t = tv[c];
            float lp2, lq2;
            asm("lg2.approx.f32 %0, %1;" : "=f"(lp2) : "f"(p));
            asm("lg2.approx.f32 %0, %1;" : "=f"(lq2) : "f"(1.0f - p));
            lp2 = fmaxf(lp2, LOG2_CLAMP);
            lq2 = fmaxf(lq2, LOG2_CLAMP);
            const float term = fmaf(t, lp2 - lq2, lq2);   // log2 domain
            lsum = fmaf(wgt, term, lsum);
        }
    }
    lsum *= LN2F;

    __shared__ double s_acc;
    if (threadIdx.x == 0) s_acc = 0.0;
    __syncthreads();

    #pragma unroll
    for (int o = 16; o; o >>= 1) lsum += __shfl_xor_sync(0xffffffffu, lsum, o);
    if ((threadIdx.x & 31) == 0) atomicAdd(&s_acc, (double)lsum);
    __syncthreads();

    if (threadIdx.x == 0) {
        atomicAdd(&g_acc, s_acc);
        __threadfence();
        const unsigned t = atomicAdd(&g_done, 1u);
        if (t == gridDim.x - 1) {
            const double total = atomicAdd(&g_acc, 0.0);
            out[0] = (float)(-total * inv_n);
        }
    }
}

extern "C" void kernel_launch(void* const* d_in, const int* in_sizes, int n_in,
                              void* d_out, int out_size)
{
    const float* inp = (const float*)d_in[0];
    const float* tgt = (const float*)d_in[1];
    float* out = (float*)d_out;

    const int n       = in_sizes[1];       // B*T*W*W
    const int nframes = n >> 16;

    frame_stats_kernel<<<nframes, 1024>>>(tgt);
    loss_kernel<<<nframes * TILES_PER_FRAME, 256>>>(inp, tgt, out, 1.0 / (double)n);
}